// round 10
// baseline (speedup 1.0000x reference)
#include <cuda_runtime.h>
#include <cuda_fp16.h>
#include <cuda_bf16.h>
#include <cstdint>
#include <limits.h>

#define NMAX 100000
#define NPAD 100096   // 782 * 128: GEMM A-tile cp.async never reads past arrays
#define EMAX 1600000
#define NGR  64
#define FDIM 128

// ---------------- device scratch ----------------
static __device__ __nv_bfloat16  g_Xh[(size_t)NPAD * FDIM];
static __device__ __half         g_Th[(size_t)NPAD * FDIM];
static __device__ __nv_bfloat16  g_Gh[(size_t)NPAD * FDIM];
static __device__ float          g_G[(size_t)NMAX * 64];
static __device__ __nv_bfloat16  g_W1h[128 * 128], g_W1l[128 * 128];
static __device__ __nv_bfloat16  g_W2h[128 * 128], g_W2l[128 * 128];
static __device__ __nv_bfloat16  g_W3h[128 * 64],  g_W3l[128 * 64];
static __device__ int    g_cnt[NMAX];
static __device__ int    g_rowptr[NMAX + 1];
static __device__ int    g_cursor[NMAX];
static __device__ int2   g_edge[EMAX];     // interleaved {src, weight-bits}
static __device__ float  g_dinv[NMAX];
static __device__ float  g_selfw[NMAX];
static __device__ int    g_gstart[NGR];
static __device__ int    g_gend[NGR];
static __device__ int    g_bsum[256];
static __device__ int    g_is64;
static __device__ int    g_src32[EMAX];
static __device__ int    g_dst32[EMAX];

// ---------------- preprocessing ----------------
__global__ void k_init_detect(const void* ei, int e, int n) {
    int i = blockIdx.x * blockDim.x + threadIdx.x;
    if (i < n) g_cnt[i] = 0;
    if (i < NGR) { g_gstart[i] = INT_MAX; g_gend[i] = 0; }
    if (blockIdx.x == 0 && threadIdx.x == 0) {
        const long long* p = (const long long*)ei;
        int ok = 1;
        int m = e < 64 ? e : 64;
        for (int k = 0; k < m; k++) {
            long long v = p[k];
            if (v < 0 || v >= (long long)n) ok = 0;
        }
        g_is64 = ok;
    }
}

__global__ void k_hist(const void* ei, int e) {
    int i = blockIdx.x * blockDim.x + threadIdx.x;
    if (i >= e) return;
    int s, d;
    if (g_is64) {
        const long long* p = (const long long*)ei;
        s = (int)p[i]; d = (int)p[(size_t)e + i];
    } else {
        const int* p = (const int*)ei;
        s = p[i]; d = p[(size_t)e + i];
    }
    g_src32[i] = s;
    g_dst32[i] = d;
    atomicAdd(&g_cnt[d], 1);
}

// merged: x fp32->bf16 convert  +  W split (independent elementwise work)
__global__ void k_prep(const float* __restrict__ x, int total4,
                       const float* __restrict__ W1, const float* __restrict__ W2,
                       const float* __restrict__ W3) {
    int i = blockIdx.x * blockDim.x + threadIdx.x;
    if (i < total4) {
        float4 v = ((const float4*)x)[i];
        __nv_bfloat162 a = __float22bfloat162_rn(make_float2(v.x, v.y));
        __nv_bfloat162 b = __float22bfloat162_rn(make_float2(v.z, v.w));
        uint2 o; o.x = *(uint32_t*)&a; o.y = *(uint32_t*)&b;
        ((uint2*)g_Xh)[i] = o;
    }
    if (i < 40960) {
        float v; __nv_bfloat16 *ph, *pl; int off;
        if (i < 16384)      { v = W1[i];          ph = g_W1h; pl = g_W1l; off = i; }
        else if (i < 32768) { v = W2[i - 16384];  ph = g_W2h; pl = g_W2l; off = i - 16384; }
        else                { v = W3[i - 32768];  ph = g_W3h; pl = g_W3l; off = i - 32768; }
        __nv_bfloat16 h = __float2bfloat16(v);
        ph[off] = h;
        pl[off] = __float2bfloat16(v - __bfloat162float(h));
    }
}

__global__ void k_chunk_sums(int n) {
    __shared__ int sh[256];
    int base = blockIdx.x * 1024 + threadIdx.x * 4;
    int s = 0;
#pragma unroll
    for (int j = 0; j < 4; j++) {
        int id = base + j;
        if (id < n) s += g_cnt[id];
    }
    sh[threadIdx.x] = s;
    __syncthreads();
    for (int d = 128; d > 0; d >>= 1) {
        if (threadIdx.x < d) sh[threadIdx.x] += sh[threadIdx.x + d];
        __syncthreads();
    }
    if (threadIdx.x == 0) g_bsum[blockIdx.x] = sh[0];
}

__global__ void k_scan_top(int nch, int n) {
    __shared__ int sh[128];
    int t = threadIdx.x;
    int v = (t < nch) ? g_bsum[t] : 0;
    sh[t] = v;
    __syncthreads();
    for (int d = 1; d < 128; d <<= 1) {
        int x = (t >= d) ? sh[t - d] : 0;
        __syncthreads();
        sh[t] += x;
        __syncthreads();
    }
    if (t < nch) g_bsum[t] = sh[t] - v;
    if (t == nch - 1) g_rowptr[n] = sh[t];
}

__global__ void k_scan_chunks(int n) {
    __shared__ int sh[256];
    int t = threadIdx.x;
    int idx0 = blockIdx.x * 1024 + t * 4;
    int c[4]; int tot = 0;
#pragma unroll
    for (int j = 0; j < 4; j++) {
        int id = idx0 + j;
        c[j] = (id < n) ? g_cnt[id] : 0;
        tot += c[j];
    }
    sh[t] = tot;
    __syncthreads();
    for (int d = 1; d < 256; d <<= 1) {
        int v = (t >= d) ? sh[t - d] : 0;
        __syncthreads();
        sh[t] += v;
        __syncthreads();
    }
    int run = g_bsum[blockIdx.x] + sh[t] - tot;
#pragma unroll
    for (int j = 0; j < 4; j++) {
        int id = idx0 + j;
        if (id < n) g_rowptr[id] = run;
        run += c[j];
    }
}

__global__ void k_dinv_bounds(const void* batch, int n) {
    int i = blockIdx.x * blockDim.x + threadIdx.x;
    if (i >= n) return;
    float deg = (float)(g_cnt[i] + 1);
    float di = rsqrtf(deg);
    g_dinv[i] = di;
    g_selfw[i] = di * di;
    g_cursor[i] = g_rowptr[i];

    int b, bp, bn_;
    if (g_is64) {
        const long long* p = (const long long*)batch;
        b = (int)p[i];
        bp = (i > 0) ? (int)p[i - 1] : -1;
        bn_ = (i < n - 1) ? (int)p[i + 1] : -1;
    } else {
        const int* p = (const int*)batch;
        b = p[i];
        bp = (i > 0) ? p[i - 1] : -1;
        bn_ = (i < n - 1) ? p[i + 1] : -1;
    }
    if (i == 0 || bp != b) atomicMin(&g_gstart[b], i);
    if (i == n - 1 || bn_ != b) atomicMax(&g_gend[b], i + 1);
}

__global__ void k_build(int e) {
    int i = blockIdx.x * blockDim.x + threadIdx.x;
    if (i >= e) return;
    int s = g_src32[i], d = g_dst32[i];
    float w = g_dinv[s] * g_dinv[d];
    int pos = atomicAdd(&g_cursor[d], 1);
    g_edge[pos] = make_int2(s, __float_as_int(w));
}

// ---------------- bf16 tensor-core GEMM (W smem-resident, all tiles cp.async) ----------------
__device__ __forceinline__ void mma_bf16(float* c, const uint32_t* a, const uint32_t* b) {
    asm volatile("mma.sync.aligned.m16n8k16.row.col.f32.bf16.bf16.f32 "
        "{%0,%1,%2,%3}, {%4,%5,%6,%7}, {%8,%9}, {%0,%1,%2,%3};"
        : "+f"(c[0]), "+f"(c[1]), "+f"(c[2]), "+f"(c[3])
        : "r"(a[0]), "r"(a[1]), "r"(a[2]), "r"(a[3]), "r"(b[0]), "r"(b[1]));
}
__device__ __forceinline__ void ldsm_x4(uint32_t* r, uint32_t addr) {
    asm volatile("ldmatrix.sync.aligned.m8n8.x4.shared.b16 {%0,%1,%2,%3}, [%4];"
        : "=r"(r[0]), "=r"(r[1]), "=r"(r[2]), "=r"(r[3]) : "r"(addr));
}
__device__ __forceinline__ void ldsm_x2t(uint32_t* r, uint32_t addr) {
    asm volatile("ldmatrix.sync.aligned.m8n8.x2.trans.shared.b16 {%0,%1}, [%2];"
        : "=r"(r[0]), "=r"(r[1]) : "r"(addr));
}
__device__ __forceinline__ void cp_async16(uint32_t dst, const void* src) {
    asm volatile("cp.async.ca.shared.global [%0], [%1], 16;" :: "r"(dst), "l"(src));
}

template <int BN>
__global__ __launch_bounds__(256) void k_gemm_bf(const __nv_bfloat16* __restrict__ A,
                                                 const __nv_bfloat16* __restrict__ Wh,
                                                 const __nv_bfloat16* __restrict__ Wl,
                                                 __half* __restrict__ C, int M) {
    constexpr int NJ = BN / 16;
    constexpr int WS = BN + 8;
    extern __shared__ __nv_bfloat16 smem[];
    __nv_bfloat16* sWh = smem;
    __nv_bfloat16* sWl = smem + 128 * WS;
    __nv_bfloat16* sA  = smem + 2 * 128 * WS;

    int tid = threadIdx.x;
    int w = tid >> 5, lane = tid & 31;
    int grp = lane >> 2, tig = lane & 3;
    int wm = (w & 3) * 32;
    int wn = (w >> 2) * (NJ * 8);
    int m0 = blockIdx.x * 128;
    int l15 = lane & 15;

    // group 0: W hi+lo + A tile 0
#pragma unroll
    for (int i = tid; i < 128 * BN / 8; i += 256) {
        int r = i / (BN / 8), q = i % (BN / 8);
        cp_async16((uint32_t)__cvta_generic_to_shared(&sWh[r * WS + q * 8]), &Wh[r * BN + q * 8]);
        cp_async16((uint32_t)__cvta_generic_to_shared(&sWl[r * WS + q * 8]), &Wl[r * BN + q * 8]);
    }
#pragma unroll
    for (int cch = 0; cch < 2; cch++) {
        int idx = tid + cch * 256;
        int row = idx >> 2, q = idx & 3;
        cp_async16((uint32_t)__cvta_generic_to_shared(&sA[row * 40 + q * 8]),
                   &A[(size_t)(m0 + row) * 128 + q * 8]);
    }
    asm volatile("cp.async.commit_group;");
#pragma unroll
    for (int t = 1; t < 4; t++) {
#pragma unroll
        for (int cch = 0; cch < 2; cch++) {
            int idx = tid + cch * 256;
            int row = idx >> 2, q = idx & 3;
            cp_async16((uint32_t)__cvta_generic_to_shared(&sA[(t * 128 + row) * 40 + q * 8]),
                       &A[(size_t)(m0 + row) * 128 + t * 32 + q * 8]);
        }
        asm volatile("cp.async.commit_group;");
    }

    float c[2][NJ][4];
#pragma unroll
    for (int i = 0; i < 2; i++)
#pragma unroll
        for (int j = 0; j < NJ; j++)
#pragma unroll
            for (int q = 0; q < 4; q++) c[i][j][q] = 0.f;

#pragma unroll
    for (int t = 0; t < 4; t++) {
        if (t == 0)      asm volatile("cp.async.wait_group 3;");
        else if (t == 1) asm volatile("cp.async.wait_group 2;");
        else if (t == 2) asm volatile("cp.async.wait_group 1;");
        else             asm volatile("cp.async.wait_group 0;");
        __syncthreads();
#pragma unroll
        for (int k16 = 0; k16 < 32; k16 += 16) {
            int krow = t * 32 + k16;
            uint32_t a[2][4];
#pragma unroll
            for (int i = 0; i < 2; i++) {
                uint32_t addr = (uint32_t)__cvta_generic_to_shared(
                    &sA[(t * 128 + wm + i * 16 + l15) * 40 + k16 + (lane >> 4) * 8]);
                ldsm_x4(a[i], addr);
            }
            uint32_t b[NJ][2];
#pragma unroll
            for (int j = 0; j < NJ; j++) {
                uint32_t addr = (uint32_t)__cvta_generic_to_shared(
                    &sWh[(krow + l15) * WS + wn + j * 8]);
                ldsm_x2t(b[j], addr);
            }
#pragma unroll
            for (int i = 0; i < 2; i++)
#pragma unroll
                for (int j = 0; j < NJ; j++) mma_bf16(c[i][j], a[i], b[j]);
#pragma unroll
            for (int j = 0; j < NJ; j++) {
                uint32_t addr = (uint32_t)__cvta_generic_to_shared(
                    &sWl[(krow + l15) * WS + wn + j * 8]);
                ldsm_x2t(b[j], addr);
            }
#pragma unroll
            for (int i = 0; i < 2; i++)
#pragma unroll
                for (int j = 0; j < NJ; j++) mma_bf16(c[i][j], a[i], b[j]);
        }
    }

#pragma unroll
    for (int i = 0; i < 2; i++) {
        int r0 = m0 + wm + i * 16 + grp;
        int r1 = r0 + 8;
#pragma unroll
        for (int j = 0; j < NJ; j++) {
            int col = wn + j * 8 + tig * 2;
            if (r0 < M) *(__half2*)&C[(size_t)r0 * BN + col] = __floats2half2_rn(c[i][j][0], c[i][j][1]);
            if (r1 < M) *(__half2*)&C[(size_t)r1 * BN + col] = __floats2half2_rn(c[i][j][2], c[i][j][3]);
        }
    }
}

// ---------------- aggregation (bounded-unroll gathers: no padded row-0 loads) ----------------
__device__ __forceinline__ float4 h4_to_f4(uint2 v, float4 acc, float w) {
    float2 a = __half22float2(*(__half2*)&v.x);
    float2 b = __half22float2(*(__half2*)&v.y);
    acc.x += w * a.x; acc.y += w * a.y; acc.z += w * b.x; acc.w += w * b.y;
    return acc;
}

__global__ __launch_bounds__(256) void k_agg128(const __half* __restrict__ H,
                                                const float* __restrict__ bias,
                                                __nv_bfloat16* __restrict__ out, int n) {
    int warp = (blockIdx.x * blockDim.x + threadIdx.x) >> 5;
    if (warp >= n) return;
    int lane = threadIdx.x & 31;
    const uint2* H2 = (const uint2*)H;
    float sw = g_selfw[warp];
    float4 acc = h4_to_f4(H2[(size_t)warp * 32 + lane], make_float4(0, 0, 0, 0), sw);
    int beg = g_rowptr[warp], end = g_rowptr[warp + 1];
    for (int base = beg; base < end; base += 32) {
        int m = end - base; if (m > 32) m = 32;
        int s = 0; float wgt = 0.f;
        if (lane < m) { int2 ed = g_edge[base + lane]; s = ed.x; wgt = __int_as_float(ed.y); }
        for (int j = 0; j < m; j += 8) {
            int mu = m - j; if (mu > 8) mu = 8;      // valid gathers only in this batch
            int si[8]; float wi[8]; uint2 gv[8];
#pragma unroll
            for (int u = 0; u < 8; u++) {
                si[u] = __shfl_sync(0xffffffffu, s, j + u);
                wi[u] = __shfl_sync(0xffffffffu, wgt, j + u);
                gv[u] = make_uint2(0u, 0u);
            }
#pragma unroll
            for (int u = 0; u < 8; u++)
                if (u < mu) gv[u] = H2[(size_t)si[u] * 32 + lane];
#pragma unroll
            for (int u = 0; u < 8; u++) acc = h4_to_f4(gv[u], acc, wi[u]);
        }
    }
    float4 b4 = ((const float4*)bias)[lane];
    acc.x = fmaxf(acc.x + b4.x, 0.f);
    acc.y = fmaxf(acc.y + b4.y, 0.f);
    acc.z = fmaxf(acc.z + b4.z, 0.f);
    acc.w = fmaxf(acc.w + b4.w, 0.f);
    __nv_bfloat162 o0 = __float22bfloat162_rn(make_float2(acc.x, acc.y));
    __nv_bfloat162 o1 = __float22bfloat162_rn(make_float2(acc.z, acc.w));
    uint2 o; o.x = *(uint32_t*)&o0; o.y = *(uint32_t*)&o1;
    ((uint2*)out)[(size_t)warp * 32 + lane] = o;
}

__global__ __launch_bounds__(256) void k_agg64(const __half* __restrict__ H,
                                               const float* __restrict__ bias,
                                               float* __restrict__ out, int n) {
    int warp = (blockIdx.x * blockDim.x + threadIdx.x) >> 5;
    if (warp >= n) return;
    int lane = threadIdx.x & 31;
    const uint32_t* H1 = (const uint32_t*)H;
    float sw = g_selfw[warp];
    uint32_t hv = H1[(size_t)warp * 32 + lane];
    float2 f0 = __half22float2(*(__half2*)&hv);
    float2 acc = make_float2(sw * f0.x, sw * f0.y);
    int beg = g_rowptr[warp], end = g_rowptr[warp + 1];
    for (int base = beg; base < end; base += 32) {
        int m = end - base; if (m > 32) m = 32;
        int s = 0; float wgt = 0.f;
        if (lane < m) { int2 ed = g_edge[base + lane]; s = ed.x; wgt = __int_as_float(ed.y); }
        for (int j = 0; j < m; j += 8) {
            int mu = m - j; if (mu > 8) mu = 8;
            int si[8]; float wi[8]; uint32_t gv[8];
#pragma unroll
            for (int u = 0; u < 8; u++) {
                si[u] = __shfl_sync(0xffffffffu, s, j + u);
                wi[u] = __shfl_sync(0xffffffffu, wgt, j + u);
                gv[u] = 0u;
            }
#pragma unroll
            for (int u = 0; u < 8; u++)
                if (u < mu) gv[u] = H1[(size_t)si[u] * 32 + lane];
#pragma unroll
            for (int u = 0; u < 8; u++) {
                float2 a0 = __half22float2(*(__half2*)&gv[u]);
                acc.x += wi[u] * a0.x; acc.y += wi[u] * a0.y;
            }
        }
    }
    float2 b2 = ((const float2*)bias)[lane];
    acc.x += b2.x; acc.y += b2.y;
    ((float2*)out)[(size_t)warp * 32 + lane] = acc;
}

// ---------------- global mean pool ----------------
__global__ void k_pool(const float* __restrict__ Hout, float* __restrict__ out) {
    int g = blockIdx.x;
    int t = threadIdx.x;
    int f = t & 63, grp = t >> 6;
    __shared__ float sh[256];
    int s = g_gstart[g], e = g_gend[g];
    float acc = 0.f;
    if (s < e) {
        for (int i = s + grp; i < e; i += 4) acc += Hout[(size_t)i * 64 + f];
    }
    sh[t] = acc;
    __syncthreads();
    if (grp == 0) {
        float v = sh[f] + sh[64 + f] + sh[128 + f] + sh[192 + f];
        int cnt = (s < e) ? (e - s) : 0;
        float denom = (cnt > 0) ? (float)cnt : 1.f;
        out[g * 64 + f] = v / denom;
    }
}

// ---------------- launch ----------------
extern "C" void kernel_launch(void* const* d_in, const int* in_sizes, int n_in,
                              void* d_out, int out_size) {
    const float* x  = (const float*)d_in[0];
    const void*  ei = d_in[1];
    const void*  batch = d_in[2];
    const float* W1 = (const float*)d_in[3];
    const float* b1 = (const float*)d_in[4];
    const float* W2 = (const float*)d_in[5];
    const float* b2 = (const float*)d_in[6];
    const float* W3 = (const float*)d_in[7];
    const float* b3 = (const float*)d_in[8];
    float* out = (float*)d_out;

    int n = in_sizes[0] / FDIM;
    int e = in_sizes[1] / 2;
    if (n > NMAX) n = NMAX;
    if (e > EMAX) e = EMAX;

    int gn  = (n + 255) / 256;
    int ge  = (e + 255) / 256;
    int nch = (n + 1023) / 1024;

    void* p;
    cudaGetSymbolAddress(&p, g_Th);  __half* pTh = (__half*)p;
    cudaGetSymbolAddress(&p, g_Gh);  __nv_bfloat16* pGh = (__nv_bfloat16*)p;
    cudaGetSymbolAddress(&p, g_Xh);  __nv_bfloat16* pXh = (__nv_bfloat16*)p;
    cudaGetSymbolAddress(&p, g_G);   float* pG = (float*)p;
    cudaGetSymbolAddress(&p, g_W1h); __nv_bfloat16* pW1h = (__nv_bfloat16*)p;
    cudaGetSymbolAddress(&p, g_W1l); __nv_bfloat16* pW1l = (__nv_bfloat16*)p;
    cudaGetSymbolAddress(&p, g_W2h); __nv_bfloat16* pW2h = (__nv_bfloat16*)p;
    cudaGetSymbolAddress(&p, g_W2l); __nv_bfloat16* pW2l = (__nv_bfloat16*)p;
    cudaGetSymbolAddress(&p, g_W3h); __nv_bfloat16* pW3h = (__nv_bfloat16*)p;
    cudaGetSymbolAddress(&p, g_W3l); __nv_bfloat16* pW3l = (__nv_bfloat16*)p;

    const int SMEM128 = 2 * 128 * (128 + 8) * 2 + 4 * 128 * 40 * 2;  // 110592
    const int SMEM64  = 2 * 128 * (64 + 8) * 2 + 4 * 128 * 40 * 2;   // 77824
    cudaFuncSetAttribute(k_gemm_bf<128>, cudaFuncAttributeMaxDynamicSharedMemorySize, SMEM128);
    cudaFuncSetAttribute(k_gemm_bf<64>,  cudaFuncAttributeMaxDynamicSharedMemorySize, SMEM64);

    int ggemm = (n + 127) / 128;
    int gagg  = (n * 32 + 255) / 256;

    k_init_detect<<<gn, 256>>>(ei, e, n);                               // 1
    k_hist<<<ge, 256>>>(ei, e);                                         // 2
    k_prep<<<(n * FDIM / 4 + 255) / 256, 256>>>(x, n * FDIM / 4, W1, W2, W3);  // 3
    k_gemm_bf<128><<<ggemm, 256, SMEM128>>>(pXh, pW1h, pW1l, pTh, n);   // 4 <- ncu slot
    k_chunk_sums<<<nch, 256>>>(n);                                      // 5
    k_scan_top<<<1, 128>>>(nch, n);                                     // 6
    k_scan_chunks<<<nch, 256>>>(n);                                     // 7
    k_dinv_bounds<<<gn, 256>>>(batch, n);                               // 8
    k_build<<<ge, 256>>>(e);                                            // 9
    k_agg128<<<gagg, 256>>>(pTh, b1, pGh, n);                           // 10
    k_gemm_bf<128><<<ggemm, 256, SMEM128>>>(pGh, pW2h, pW2l, pTh, n);   // 11
    k_agg128<<<gagg, 256>>>(pTh, b2, pGh, n);                           // 12
    k_gemm_bf<64><<<ggemm, 256, SMEM64>>>(pGh, pW3h, pW3l, pTh, n);     // 13
    k_agg64<<<gagg, 256>>>(pTh, b3, pG, n);                             // 14
    k_pool<<<NGR, 256>>>(pG, out);                                      // 15
}

// round 11
// speedup vs baseline: 1.0286x; 1.0286x over previous
#include <cuda_runtime.h>
#include <cuda_fp16.h>
#include <cuda_bf16.h>
#include <cstdint>
#include <limits.h>

#define NMAX 100000
#define NPAD 100096   // 782 * 128: GEMM A-tile cp.async never reads past arrays
#define EMAX 1600000
#define NGR  64
#define FDIM 128

// ---------------- device scratch ----------------
static __device__ __nv_bfloat16  g_Xh[(size_t)NPAD * FDIM];
static __device__ __half         g_Th[(size_t)NPAD * FDIM];
static __device__ __nv_bfloat16  g_Gh[(size_t)NPAD * FDIM];
static __device__ float          g_G[(size_t)NMAX * 64];
static __device__ __nv_bfloat16  g_W1h[128 * 128], g_W1l[128 * 128];
static __device__ __nv_bfloat16  g_W2h[128 * 128], g_W2l[128 * 128];
static __device__ __nv_bfloat16  g_W3h[128 * 64],  g_W3l[128 * 64];
static __device__ int    g_cnt[NMAX];
static __device__ int    g_rowptr[NMAX + 1];
static __device__ int    g_cursor[NMAX];
static __device__ int2   g_edge[EMAX];     // interleaved {src, weight-bits}
static __device__ float  g_dinv[NMAX];
static __device__ float  g_selfw[NMAX];
static __device__ int    g_gstart[NGR];
static __device__ int    g_gend[NGR];
static __device__ int    g_bsum[256];
static __device__ int    g_is64;
static __device__ int    g_src32[EMAX];
static __device__ int    g_dst32[EMAX];

// ---------------- preprocessing ----------------
__global__ void k_init_detect(const void* ei, int e, int n) {
    int i = blockIdx.x * blockDim.x + threadIdx.x;
    if (i < n) g_cnt[i] = 0;
    if (i < NGR) { g_gstart[i] = INT_MAX; g_gend[i] = 0; }
    if (blockIdx.x == 0 && threadIdx.x == 0) {
        const long long* p = (const long long*)ei;
        int ok = 1;
        int m = e < 64 ? e : 64;
        for (int k = 0; k < m; k++) {
            long long v = p[k];
            if (v < 0 || v >= (long long)n) ok = 0;
        }
        g_is64 = ok;
    }
}

__global__ void k_hist(const void* ei, int e) {
    int i = blockIdx.x * blockDim.x + threadIdx.x;
    if (i >= e) return;
    int s, d;
    if (g_is64) {
        const long long* p = (const long long*)ei;
        s = (int)p[i]; d = (int)p[(size_t)e + i];
    } else {
        const int* p = (const int*)ei;
        s = p[i]; d = p[(size_t)e + i];
    }
    g_src32[i] = s;
    g_dst32[i] = d;
    atomicAdd(&g_cnt[d], 1);
}

// merged: x fp32->bf16 convert  +  W split (independent elementwise work)
__global__ void k_prep(const float* __restrict__ x, int total4,
                       const float* __restrict__ W1, const float* __restrict__ W2,
                       const float* __restrict__ W3) {
    int i = blockIdx.x * blockDim.x + threadIdx.x;
    if (i < total4) {
        float4 v = ((const float4*)x)[i];
        __nv_bfloat162 a = __float22bfloat162_rn(make_float2(v.x, v.y));
        __nv_bfloat162 b = __float22bfloat162_rn(make_float2(v.z, v.w));
        uint2 o; o.x = *(uint32_t*)&a; o.y = *(uint32_t*)&b;
        ((uint2*)g_Xh)[i] = o;
    }
    if (i < 40960) {
        float v; __nv_bfloat16 *ph, *pl; int off;
        if (i < 16384)      { v = W1[i];          ph = g_W1h; pl = g_W1l; off = i; }
        else if (i < 32768) { v = W2[i - 16384];  ph = g_W2h; pl = g_W2l; off = i - 16384; }
        else                { v = W3[i - 32768];  ph = g_W3h; pl = g_W3l; off = i - 32768; }
        __nv_bfloat16 h = __float2bfloat16(v);
        ph[off] = h;
        pl[off] = __float2bfloat16(v - __bfloat162float(h));
    }
}

__global__ void k_chunk_sums(int n) {
    __shared__ int sh[256];
    int base = blockIdx.x * 1024 + threadIdx.x * 4;
    int s = 0;
#pragma unroll
    for (int j = 0; j < 4; j++) {
        int id = base + j;
        if (id < n) s += g_cnt[id];
    }
    sh[threadIdx.x] = s;
    __syncthreads();
    for (int d = 128; d > 0; d >>= 1) {
        if (threadIdx.x < d) sh[threadIdx.x] += sh[threadIdx.x + d];
        __syncthreads();
    }
    if (threadIdx.x == 0) g_bsum[blockIdx.x] = sh[0];
}

__global__ void k_scan_top(int nch, int n) {
    __shared__ int sh[128];
    int t = threadIdx.x;
    int v = (t < nch) ? g_bsum[t] : 0;
    sh[t] = v;
    __syncthreads();
    for (int d = 1; d < 128; d <<= 1) {
        int x = (t >= d) ? sh[t - d] : 0;
        __syncthreads();
        sh[t] += x;
        __syncthreads();
    }
    if (t < nch) g_bsum[t] = sh[t] - v;
    if (t == nch - 1) g_rowptr[n] = sh[t];
}

__global__ void k_scan_chunks(int n) {
    __shared__ int sh[256];
    int t = threadIdx.x;
    int idx0 = blockIdx.x * 1024 + t * 4;
    int c[4]; int tot = 0;
#pragma unroll
    for (int j = 0; j < 4; j++) {
        int id = idx0 + j;
        c[j] = (id < n) ? g_cnt[id] : 0;
        tot += c[j];
    }
    sh[t] = tot;
    __syncthreads();
    for (int d = 1; d < 256; d <<= 1) {
        int v = (t >= d) ? sh[t - d] : 0;
        __syncthreads();
        sh[t] += v;
        __syncthreads();
    }
    int run = g_bsum[blockIdx.x] + sh[t] - tot;
#pragma unroll
    for (int j = 0; j < 4; j++) {
        int id = idx0 + j;
        if (id < n) g_rowptr[id] = run;
        run += c[j];
    }
}

__global__ void k_dinv_bounds(const void* batch, int n) {
    int i = blockIdx.x * blockDim.x + threadIdx.x;
    if (i >= n) return;
    float deg = (float)(g_cnt[i] + 1);
    float di = rsqrtf(deg);
    g_dinv[i] = di;
    g_selfw[i] = di * di;
    g_cursor[i] = g_rowptr[i];

    int b, bp, bn_;
    if (g_is64) {
        const long long* p = (const long long*)batch;
        b = (int)p[i];
        bp = (i > 0) ? (int)p[i - 1] : -1;
        bn_ = (i < n - 1) ? (int)p[i + 1] : -1;
    } else {
        const int* p = (const int*)batch;
        b = p[i];
        bp = (i > 0) ? p[i - 1] : -1;
        bn_ = (i < n - 1) ? p[i + 1] : -1;
    }
    if (i == 0 || bp != b) atomicMin(&g_gstart[b], i);
    if (i == n - 1 || bn_ != b) atomicMax(&g_gend[b], i + 1);
}

__global__ void k_build(int e) {
    int i = blockIdx.x * blockDim.x + threadIdx.x;
    if (i >= e) return;
    int s = g_src32[i], d = g_dst32[i];
    float w = g_dinv[s] * g_dinv[d];
    int pos = atomicAdd(&g_cursor[d], 1);
    g_edge[pos] = make_int2(s, __float_as_int(w));
}

// ---------------- bf16 tensor-core GEMM (W smem-resident, all tiles cp.async) ----------------
__device__ __forceinline__ void mma_bf16(float* c, const uint32_t* a, const uint32_t* b) {
    asm volatile("mma.sync.aligned.m16n8k16.row.col.f32.bf16.bf16.f32 "
        "{%0,%1,%2,%3}, {%4,%5,%6,%7}, {%8,%9}, {%0,%1,%2,%3};"
        : "+f"(c[0]), "+f"(c[1]), "+f"(c[2]), "+f"(c[3])
        : "r"(a[0]), "r"(a[1]), "r"(a[2]), "r"(a[3]), "r"(b[0]), "r"(b[1]));
}
__device__ __forceinline__ void ldsm_x4(uint32_t* r, uint32_t addr) {
    asm volatile("ldmatrix.sync.aligned.m8n8.x4.shared.b16 {%0,%1,%2,%3}, [%4];"
        : "=r"(r[0]), "=r"(r[1]), "=r"(r[2]), "=r"(r[3]) : "r"(addr));
}
__device__ __forceinline__ void ldsm_x2t(uint32_t* r, uint32_t addr) {
    asm volatile("ldmatrix.sync.aligned.m8n8.x2.trans.shared.b16 {%0,%1}, [%2];"
        : "=r"(r[0]), "=r"(r[1]) : "r"(addr));
}
__device__ __forceinline__ void cp_async16(uint32_t dst, const void* src) {
    asm volatile("cp.async.ca.shared.global [%0], [%1], 16;" :: "r"(dst), "l"(src));
}

template <int BN>
__global__ __launch_bounds__(256) void k_gemm_bf(const __nv_bfloat16* __restrict__ A,
                                                 const __nv_bfloat16* __restrict__ Wh,
                                                 const __nv_bfloat16* __restrict__ Wl,
                                                 __half* __restrict__ C, int M) {
    constexpr int NJ = BN / 16;
    constexpr int WS = BN + 8;
    extern __shared__ __nv_bfloat16 smem[];
    __nv_bfloat16* sWh = smem;
    __nv_bfloat16* sWl = smem + 128 * WS;
    __nv_bfloat16* sA  = smem + 2 * 128 * WS;

    int tid = threadIdx.x;
    int w = tid >> 5, lane = tid & 31;
    int grp = lane >> 2, tig = lane & 3;
    int wm = (w & 3) * 32;
    int wn = (w >> 2) * (NJ * 8);
    int m0 = blockIdx.x * 128;
    int l15 = lane & 15;

    // group 0: W hi+lo + A tile 0
#pragma unroll
    for (int i = tid; i < 128 * BN / 8; i += 256) {
        int r = i / (BN / 8), q = i % (BN / 8);
        cp_async16((uint32_t)__cvta_generic_to_shared(&sWh[r * WS + q * 8]), &Wh[r * BN + q * 8]);
        cp_async16((uint32_t)__cvta_generic_to_shared(&sWl[r * WS + q * 8]), &Wl[r * BN + q * 8]);
    }
#pragma unroll
    for (int cch = 0; cch < 2; cch++) {
        int idx = tid + cch * 256;
        int row = idx >> 2, q = idx & 3;
        cp_async16((uint32_t)__cvta_generic_to_shared(&sA[row * 40 + q * 8]),
                   &A[(size_t)(m0 + row) * 128 + q * 8]);
    }
    asm volatile("cp.async.commit_group;");
#pragma unroll
    for (int t = 1; t < 4; t++) {
#pragma unroll
        for (int cch = 0; cch < 2; cch++) {
            int idx = tid + cch * 256;
            int row = idx >> 2, q = idx & 3;
            cp_async16((uint32_t)__cvta_generic_to_shared(&sA[(t * 128 + row) * 40 + q * 8]),
                       &A[(size_t)(m0 + row) * 128 + t * 32 + q * 8]);
        }
        asm volatile("cp.async.commit_group;");
    }

    float c[2][NJ][4];
#pragma unroll
    for (int i = 0; i < 2; i++)
#pragma unroll
        for (int j = 0; j < NJ; j++)
#pragma unroll
            for (int q = 0; q < 4; q++) c[i][j][q] = 0.f;

#pragma unroll
    for (int t = 0; t < 4; t++) {
        if (t == 0)      asm volatile("cp.async.wait_group 3;");
        else if (t == 1) asm volatile("cp.async.wait_group 2;");
        else if (t == 2) asm volatile("cp.async.wait_group 1;");
        else             asm volatile("cp.async.wait_group 0;");
        __syncthreads();
#pragma unroll
        for (int k16 = 0; k16 < 32; k16 += 16) {
            int krow = t * 32 + k16;
            uint32_t a[2][4];
#pragma unroll
            for (int i = 0; i < 2; i++) {
                uint32_t addr = (uint32_t)__cvta_generic_to_shared(
                    &sA[(t * 128 + wm + i * 16 + l15) * 40 + k16 + (lane >> 4) * 8]);
                ldsm_x4(a[i], addr);
            }
            uint32_t b[NJ][2];
#pragma unroll
            for (int j = 0; j < NJ; j++) {
                uint32_t addr = (uint32_t)__cvta_generic_to_shared(
                    &sWh[(krow + l15) * WS + wn + j * 8]);
                ldsm_x2t(b[j], addr);
            }
#pragma unroll
            for (int i = 0; i < 2; i++)
#pragma unroll
                for (int j = 0; j < NJ; j++) mma_bf16(c[i][j], a[i], b[j]);
#pragma unroll
            for (int j = 0; j < NJ; j++) {
                uint32_t addr = (uint32_t)__cvta_generic_to_shared(
                    &sWl[(krow + l15) * WS + wn + j * 8]);
                ldsm_x2t(b[j], addr);
            }
#pragma unroll
            for (int i = 0; i < 2; i++)
#pragma unroll
                for (int j = 0; j < NJ; j++) mma_bf16(c[i][j], a[i], b[j]);
        }
    }

#pragma unroll
    for (int i = 0; i < 2; i++) {
        int r0 = m0 + wm + i * 16 + grp;
        int r1 = r0 + 8;
#pragma unroll
        for (int j = 0; j < NJ; j++) {
            int col = wn + j * 8 + tig * 2;
            if (r0 < M) *(__half2*)&C[(size_t)r0 * BN + col] = __floats2half2_rn(c[i][j][0], c[i][j][1]);
            if (r1 < M) *(__half2*)&C[(size_t)r1 * BN + col] = __floats2half2_rn(c[i][j][2], c[i][j][3]);
        }
    }
}

// ---------------- aggregation ----------------
// k_agg128 v2: 2 nodes per warp (16-lane halves), uint4 row loads: one LDG.128
// serves two row-gathers. Edge order per node unchanged -> identical numerics.
__global__ __launch_bounds__(256) void k_agg128(const __half* __restrict__ H,
                                                const float* __restrict__ bias,
                                                __nv_bfloat16* __restrict__ out, int n) {
    int gw = (blockIdx.x * blockDim.x + threadIdx.x) >> 5;
    if (gw * 2 >= n) return;
    int lane = threadIdx.x & 31;
    int half = lane >> 4, l16 = lane & 15;
    int node = gw * 2 + half;
    bool active = node < n;
    int nodec = active ? node : n - 1;

    const uint4* H4 = (const uint4*)H;          // 16 uint4 per 128-half row
    uint4 hv = H4[(size_t)nodec * 16 + l16];
    float sw = g_selfw[nodec];
    float2 p0 = __half22float2(*(__half2*)&hv.x);
    float2 p1 = __half22float2(*(__half2*)&hv.y);
    float2 p2 = __half22float2(*(__half2*)&hv.z);
    float2 p3 = __half22float2(*(__half2*)&hv.w);
    float acc[8] = { sw * p0.x, sw * p0.y, sw * p1.x, sw * p1.y,
                     sw * p2.x, sw * p2.y, sw * p3.x, sw * p3.y };

    int beg = g_rowptr[nodec];
    int deg = g_rowptr[nodec + 1] - beg;
    int omax = max(deg, __shfl_xor_sync(0xffffffffu, deg, 16));

    for (int off = 0; off < omax; off += 16) {
        int m = deg - off; m = m < 0 ? 0 : (m > 16 ? 16 : m);
        int s = 0; float wgt = 0.f;
        if (l16 < m) { int2 ed = g_edge[beg + off + l16]; s = ed.x; wgt = __int_as_float(ed.y); }
#pragma unroll
        for (int j = 0; j < 16; j += 8) {
            int si[8]; float wi[8]; uint4 gv[8];
            int srcb = (half << 4) + j;
#pragma unroll
            for (int u = 0; u < 8; u++) {
                si[u] = __shfl_sync(0xffffffffu, s, srcb + u);
                wi[u] = __shfl_sync(0xffffffffu, wgt, srcb + u);
            }
#pragma unroll
            for (int u = 0; u < 8; u++) gv[u] = H4[(size_t)si[u] * 16 + l16];
#pragma unroll
            for (int u = 0; u < 8; u++) {
                float2 a = __half22float2(*(__half2*)&gv[u].x);
                float2 b = __half22float2(*(__half2*)&gv[u].y);
                float2 c = __half22float2(*(__half2*)&gv[u].z);
                float2 d = __half22float2(*(__half2*)&gv[u].w);
                acc[0] += wi[u] * a.x; acc[1] += wi[u] * a.y;
                acc[2] += wi[u] * b.x; acc[3] += wi[u] * b.y;
                acc[4] += wi[u] * c.x; acc[5] += wi[u] * c.y;
                acc[6] += wi[u] * d.x; acc[7] += wi[u] * d.y;
            }
        }
    }

    float4 b0 = ((const float4*)bias)[l16 * 2];
    float4 b1 = ((const float4*)bias)[l16 * 2 + 1];
    acc[0] = fmaxf(acc[0] + b0.x, 0.f); acc[1] = fmaxf(acc[1] + b0.y, 0.f);
    acc[2] = fmaxf(acc[2] + b0.z, 0.f); acc[3] = fmaxf(acc[3] + b0.w, 0.f);
    acc[4] = fmaxf(acc[4] + b1.x, 0.f); acc[5] = fmaxf(acc[5] + b1.y, 0.f);
    acc[6] = fmaxf(acc[6] + b1.z, 0.f); acc[7] = fmaxf(acc[7] + b1.w, 0.f);
    __nv_bfloat162 o0 = __float22bfloat162_rn(make_float2(acc[0], acc[1]));
    __nv_bfloat162 o1 = __float22bfloat162_rn(make_float2(acc[2], acc[3]));
    __nv_bfloat162 o2 = __float22bfloat162_rn(make_float2(acc[4], acc[5]));
    __nv_bfloat162 o3 = __float22bfloat162_rn(make_float2(acc[6], acc[7]));
    uint4 o;
    o.x = *(uint32_t*)&o0; o.y = *(uint32_t*)&o1;
    o.z = *(uint32_t*)&o2; o.w = *(uint32_t*)&o3;
    if (active) ((uint4*)out)[(size_t)node * 16 + l16] = o;
}

// k_agg64: R7 form (1 node/warp, unconditional unroll-8 with zero-weight pad)
__global__ __launch_bounds__(256) void k_agg64(const __half* __restrict__ H,
                                               const float* __restrict__ bias,
                                               float* __restrict__ out, int n) {
    int warp = (blockIdx.x * blockDim.x + threadIdx.x) >> 5;
    if (warp >= n) return;
    int lane = threadIdx.x & 31;
    const uint32_t* H1 = (const uint32_t*)H;
    float sw = g_selfw[warp];
    uint32_t hv = H1[(size_t)warp * 32 + lane];
    float2 f0 = __half22float2(*(__half2*)&hv);
    float2 acc = make_float2(sw * f0.x, sw * f0.y);
    int beg = g_rowptr[warp], end = g_rowptr[warp + 1];
    for (int base = beg; base < end; base += 32) {
        int m = end - base; if (m > 32) m = 32;
        int mr = (m + 7) & ~7;
        int s = 0; float wgt = 0.f;
        if (lane < m) { int2 ed = g_edge[base + lane]; s = ed.x; wgt = __int_as_float(ed.y); }
        for (int j = 0; j < mr; j += 8) {
            int si[8]; float wi[8]; uint32_t gv[8];
#pragma unroll
            for (int u = 0; u < 8; u++) {
                si[u] = __shfl_sync(0xffffffffu, s, j + u);
                wi[u] = __shfl_sync(0xffffffffu, wgt, j + u);
            }
#pragma unroll
            for (int u = 0; u < 8; u++) gv[u] = H1[(size_t)si[u] * 32 + lane];
#pragma unroll
            for (int u = 0; u < 8; u++) {
                float2 a0 = __half22float2(*(__half2*)&gv[u]);
                acc.x += wi[u] * a0.x; acc.y += wi[u] * a0.y;
            }
        }
    }
    float2 b2 = ((const float2*)bias)[lane];
    acc.x += b2.x; acc.y += b2.y;
    ((float2*)out)[(size_t)warp * 32 + lane] = acc;
}

// ---------------- global mean pool ----------------
__global__ void k_pool(const float* __restrict__ Hout, float* __restrict__ out) {
    int g = blockIdx.x;
    int t = threadIdx.x;
    int f = t & 63, grp = t >> 6;
    __shared__ float sh[256];
    int s = g_gstart[g], e = g_gend[g];
    float acc = 0.f;
    if (s < e) {
        for (int i = s + grp; i < e; i += 4) acc += Hout[(size_t)i * 64 + f];
    }
    sh[t] = acc;
    __syncthreads();
    if (grp == 0) {
        float v = sh[f] + sh[64 + f] + sh[128 + f] + sh[192 + f];
        int cnt = (s < e) ? (e - s) : 0;
        float denom = (cnt > 0) ? (float)cnt : 1.f;
        out[g * 64 + f] = v / denom;
    }
}

// ---------------- launch ----------------
extern "C" void kernel_launch(void* const* d_in, const int* in_sizes, int n_in,
                              void* d_out, int out_size) {
    const float* x  = (const float*)d_in[0];
    const void*  ei = d_in[1];
    const void*  batch = d_in[2];
    const float* W1 = (const float*)d_in[3];
    const float* b1 = (const float*)d_in[4];
    const float* W2 = (const float*)d_in[5];
    const float* b2 = (const float*)d_in[6];
    const float* W3 = (const float*)d_in[7];
    const float* b3 = (const float*)d_in[8];
    float* out = (float*)d_out;

    int n = in_sizes[0] / FDIM;
    int e = in_sizes[1] / 2;
    if (n > NMAX) n = NMAX;
    if (e > EMAX) e = EMAX;

    int gn  = (n + 255) / 256;
    int ge  = (e + 255) / 256;
    int nch = (n + 1023) / 1024;

    void* p;
    cudaGetSymbolAddress(&p, g_Th);  __half* pTh = (__half*)p;
    cudaGetSymbolAddress(&p, g_Gh);  __nv_bfloat16* pGh = (__nv_bfloat16*)p;
    cudaGetSymbolAddress(&p, g_Xh);  __nv_bfloat16* pXh = (__nv_bfloat16*)p;
    cudaGetSymbolAddress(&p, g_G);   float* pG = (float*)p;
    cudaGetSymbolAddress(&p, g_W1h); __nv_bfloat16* pW1h = (__nv_bfloat16*)p;
    cudaGetSymbolAddress(&p, g_W1l); __nv_bfloat16* pW1l = (__nv_bfloat16*)p;
    cudaGetSymbolAddress(&p, g_W2h); __nv_bfloat16* pW2h = (__nv_bfloat16*)p;
    cudaGetSymbolAddress(&p, g_W2l); __nv_bfloat16* pW2l = (__nv_bfloat16*)p;
    cudaGetSymbolAddress(&p, g_W3h); __nv_bfloat16* pW3h = (__nv_bfloat16*)p;
    cudaGetSymbolAddress(&p, g_W3l); __nv_bfloat16* pW3l = (__nv_bfloat16*)p;

    const int SMEM128 = 2 * 128 * (128 + 8) * 2 + 4 * 128 * 40 * 2;  // 110592
    const int SMEM64  = 2 * 128 * (64 + 8) * 2 + 4 * 128 * 40 * 2;   // 77824
    cudaFuncSetAttribute(k_gemm_bf<128>, cudaFuncAttributeMaxDynamicSharedMemorySize, SMEM128);
    cudaFuncSetAttribute(k_gemm_bf<64>,  cudaFuncAttributeMaxDynamicSharedMemorySize, SMEM64);

    int ggemm = (n + 127) / 128;
    int gagg  = (n * 32 + 255) / 256;                 // 1 node/warp kernels
    int gagg2 = (((n + 1) / 2) * 32 + 255) / 256;     // 2 nodes/warp k_agg128

    k_init_detect<<<gn, 256>>>(ei, e, n);                               // 1
    k_hist<<<ge, 256>>>(ei, e);                                         // 2
    k_prep<<<(n * FDIM / 4 + 255) / 256, 256>>>(x, n * FDIM / 4, W1, W2, W3);  // 3
    k_gemm_bf<128><<<ggemm, 256, SMEM128>>>(pXh, pW1h, pW1l, pTh, n);   // 4 <- ncu slot
    k_chunk_sums<<<nch, 256>>>(n);                                      // 5
    k_scan_top<<<1, 128>>>(nch, n);                                     // 6
    k_scan_chunks<<<nch, 256>>>(n);                                     // 7
    k_dinv_bounds<<<gn, 256>>>(batch, n);                               // 8
    k_build<<<ge, 256>>>(e);                                            // 9
    k_agg128<<<gagg2, 256>>>(pTh, b1, pGh, n);                          // 10
    k_gemm_bf<128><<<ggemm, 256, SMEM128>>>(pGh, pW2h, pW2l, pTh, n);   // 11
    k_agg128<<<gagg2, 256>>>(pTh, b2, pGh, n);                          // 12
    k_gemm_bf<64><<<ggemm, 256, SMEM64>>>(pGh, pW3h, pW3l, pTh, n);     // 13
    k_agg64<<<gagg, 256>>>(pTh, b3, pG, n);                             // 14
    k_pool<<<NGR, 256>>>(pG, out);                                      // 15
}

// round 12
// speedup vs baseline: 1.0686x; 1.0389x over previous
#include <cuda_runtime.h>
#include <cuda_fp16.h>
#include <cuda_bf16.h>
#include <cstdint>
#include <limits.h>

#define NMAX 100000
#define NPAD 100096   // 782 * 128: GEMM A-tile cp.async never reads past arrays
#define EMAX 1600000
#define NGR  64
#define FDIM 128
#define FLAGBIT 0x80000000u

// ---------------- device scratch ----------------
static __device__ __nv_bfloat16  g_Xh[(size_t)NPAD * FDIM];
static __device__ __half         g_Th[(size_t)NPAD * FDIM];
static __device__ __nv_bfloat16  g_Gh[(size_t)NPAD * FDIM];
static __device__ float          g_G[(size_t)NMAX * 64];
static __device__ __nv_bfloat16  g_W1h[128 * 128], g_W1l[128 * 128];
static __device__ __nv_bfloat16  g_W2h[128 * 128], g_W2l[128 * 128];
static __device__ __nv_bfloat16  g_W3h[128 * 64],  g_W3l[128 * 64];
static __device__ int    g_cntflags[NMAX + 128];   // [0..n) = cnt, [NMAX..NMAX+128) = scan flags (memset 0)
static __device__ int    g_rowptr[NMAX + 1];
static __device__ int    g_cursor[NMAX];
static __device__ int2   g_edge[EMAX];             // interleaved {src, weight-bits}
static __device__ float  g_dinv[NMAX];
static __device__ float  g_selfw[NMAX];
static __device__ int    g_gstart[NGR];
static __device__ int    g_gend[NGR];
static __device__ int    g_src32[EMAX];
static __device__ int    g_dst32[EMAX];

// ---------------- fused preprocessing ----------------
// One pass: x fp32->bf16, W split, edge histogram + int32 stash, graph bounds.
__global__ void k_fuse1(const float* __restrict__ x, const void* __restrict__ ei,
                        const void* __restrict__ batch,
                        const float* __restrict__ W1, const float* __restrict__ W2,
                        const float* __restrict__ W3, int n, int e, int total4) {
    __shared__ int s_is64;
    if (threadIdx.x == 0) {
        const long long* p = (const long long*)ei;
        int ok = 1;
        int m = e < 8 ? e : 8;
        for (int k = 0; k < m; k++) {
            long long v = p[k];
            if (v < 0 || v >= (long long)n) ok = 0;
        }
        s_is64 = ok;
    }
    __syncthreads();
    int is64 = s_is64;
    int i = blockIdx.x * blockDim.x + threadIdx.x;

    if (i < total4) {                       // x convert (n*32 threads)
        float4 v = ((const float4*)x)[i];
        __nv_bfloat162 a = __float22bfloat162_rn(make_float2(v.x, v.y));
        __nv_bfloat162 b = __float22bfloat162_rn(make_float2(v.z, v.w));
        uint2 o; o.x = *(uint32_t*)&a; o.y = *(uint32_t*)&b;
        ((uint2*)g_Xh)[i] = o;
    }
    if (i < 40960) {                        // W split
        float v; __nv_bfloat16 *ph, *pl; int off;
        if (i < 16384)      { v = W1[i];          ph = g_W1h; pl = g_W1l; off = i; }
        else if (i < 32768) { v = W2[i - 16384];  ph = g_W2h; pl = g_W2l; off = i - 16384; }
        else                { v = W3[i - 32768];  ph = g_W3h; pl = g_W3l; off = i - 32768; }
        __nv_bfloat16 h = __float2bfloat16(v);
        ph[off] = h;
        pl[off] = __float2bfloat16(v - __bfloat162float(h));
    }
    if (i < e) {                            // histogram + int32 stash
        int s, d;
        if (is64) {
            const long long* p = (const long long*)ei;
            s = (int)p[i]; d = (int)p[(size_t)e + i];
        } else {
            const int* p = (const int*)ei;
            s = p[i]; d = p[(size_t)e + i];
        }
        g_src32[i] = s;
        g_dst32[i] = d;
        atomicAdd(&g_cntflags[d], 1);
    }
    if (i < n) {                            // graph bounds: deterministic single-writer stores
        int b, bp;
        if (is64) {
            const long long* p = (const long long*)batch;
            b = (int)p[i];
            bp = (i > 0) ? (int)p[i - 1] : -1;
        } else {
            const int* p = (const int*)batch;
            b = p[i];
            bp = (i > 0) ? p[i - 1] : -1;
        }
        if (i == 0) {
            g_gstart[b] = 0;
            for (int q = 0; q < b; q++) { g_gstart[q] = 0; g_gend[q] = 0; }
        } else if (bp != b) {
            g_gend[bp] = i;
            g_gstart[b] = i;
            for (int q = bp + 1; q < b; q++) { g_gstart[q] = i; g_gend[q] = i; }
        }
        if (i == n - 1) {
            g_gend[b] = n;
            for (int q = b + 1; q < NGR; q++) { g_gstart[q] = n; g_gend[q] = n; }
        }
    }
}

// ---------------- single-kernel decoupled-lookback scan (+ dinv/selfw/cursor) ----------------
__global__ void k_scan(int n) {
    __shared__ int sh[256];
    __shared__ int s_base;
    int b = blockIdx.x, t = threadIdx.x;
    int idx0 = b * 1024 + t * 4;
    int c[4]; int tot = 0;
#pragma unroll
    for (int j = 0; j < 4; j++) {
        int id = idx0 + j;
        c[j] = (id < n) ? g_cntflags[id] : 0;
        tot += c[j];
    }
    sh[t] = tot;
    __syncthreads();
    // Hillis-Steele inclusive scan of per-thread totals
    for (int d = 1; d < 256; d <<= 1) {
        int v = (t >= d) ? sh[t - d] : 0;
        __syncthreads();
        sh[t] += v;
        __syncthreads();
    }
    int incl = sh[t];
    int agg  = sh[255];
    if (t == 0) atomicExch(&g_cntflags[NMAX + b], (int)((unsigned)agg | FLAGBIT));
    // lookback over all predecessor aggregates (all blocks resident: nch<=98<148)
    int partial = 0;
    for (int j = t; j < b; j += 256) {
        int v;
        do { v = *(volatile int*)&g_cntflags[NMAX + j]; } while (!((unsigned)v & FLAGBIT));
        partial += (int)((unsigned)v & ~FLAGBIT);
    }
    __syncthreads();
    sh[t] = partial;
    __syncthreads();
    for (int d = 128; d > 0; d >>= 1) {
        if (t < d) sh[t] += sh[t + d];
        __syncthreads();
    }
    if (t == 0) s_base = sh[0];
    __syncthreads();
    int run = s_base + incl - tot;          // exclusive prefix for this thread's first element
#pragma unroll
    for (int j = 0; j < 4; j++) {
        int id = idx0 + j;
        if (id < n) {
            g_rowptr[id] = run;
            g_cursor[id] = run;
            float di = rsqrtf((float)(c[j] + 1));
            g_dinv[id] = di;
            g_selfw[id] = di * di;
            run += c[j];
            if (id == n - 1) g_rowptr[n] = run;
        }
    }
}

__global__ void k_build(int e) {
    int i = blockIdx.x * blockDim.x + threadIdx.x;
    if (i >= e) return;
    int s = g_src32[i], d = g_dst32[i];
    float w = g_dinv[s] * g_dinv[d];
    int pos = atomicAdd(&g_cursor[d], 1);
    g_edge[pos] = make_int2(s, __float_as_int(w));
}

// ---------------- bf16 tensor-core GEMM (W smem-resident, all tiles cp.async) ----------------
__device__ __forceinline__ void mma_bf16(float* c, const uint32_t* a, const uint32_t* b) {
    asm volatile("mma.sync.aligned.m16n8k16.row.col.f32.bf16.bf16.f32 "
        "{%0,%1,%2,%3}, {%4,%5,%6,%7}, {%8,%9}, {%0,%1,%2,%3};"
        : "+f"(c[0]), "+f"(c[1]), "+f"(c[2]), "+f"(c[3])
        : "r"(a[0]), "r"(a[1]), "r"(a[2]), "r"(a[3]), "r"(b[0]), "r"(b[1]));
}
__device__ __forceinline__ void ldsm_x4(uint32_t* r, uint32_t addr) {
    asm volatile("ldmatrix.sync.aligned.m8n8.x4.shared.b16 {%0,%1,%2,%3}, [%4];"
        : "=r"(r[0]), "=r"(r[1]), "=r"(r[2]), "=r"(r[3]) : "r"(addr));
}
__device__ __forceinline__ void ldsm_x2t(uint32_t* r, uint32_t addr) {
    asm volatile("ldmatrix.sync.aligned.m8n8.x2.trans.shared.b16 {%0,%1}, [%2];"
        : "=r"(r[0]), "=r"(r[1]) : "r"(addr));
}
__device__ __forceinline__ void cp_async16(uint32_t dst, const void* src) {
    asm volatile("cp.async.ca.shared.global [%0], [%1], 16;" :: "r"(dst), "l"(src));
}

template <int BN>
__global__ __launch_bounds__(256) void k_gemm_bf(const __nv_bfloat16* __restrict__ A,
                                                 const __nv_bfloat16* __restrict__ Wh,
                                                 const __nv_bfloat16* __restrict__ Wl,
                                                 __half* __restrict__ C, int M) {
    constexpr int NJ = BN / 16;
    constexpr int WS = BN + 8;
    extern __shared__ __nv_bfloat16 smem[];
    __nv_bfloat16* sWh = smem;
    __nv_bfloat16* sWl = smem + 128 * WS;
    __nv_bfloat16* sA  = smem + 2 * 128 * WS;

    int tid = threadIdx.x;
    int w = tid >> 5, lane = tid & 31;
    int grp = lane >> 2, tig = lane & 3;
    int wm = (w & 3) * 32;
    int wn = (w >> 2) * (NJ * 8);
    int m0 = blockIdx.x * 128;
    int l15 = lane & 15;

#pragma unroll
    for (int i = tid; i < 128 * BN / 8; i += 256) {
        int r = i / (BN / 8), q = i % (BN / 8);
        cp_async16((uint32_t)__cvta_generic_to_shared(&sWh[r * WS + q * 8]), &Wh[r * BN + q * 8]);
        cp_async16((uint32_t)__cvta_generic_to_shared(&sWl[r * WS + q * 8]), &Wl[r * BN + q * 8]);
    }
#pragma unroll
    for (int cch = 0; cch < 2; cch++) {
        int idx = tid + cch * 256;
        int row = idx >> 2, q = idx & 3;
        cp_async16((uint32_t)__cvta_generic_to_shared(&sA[row * 40 + q * 8]),
                   &A[(size_t)(m0 + row) * 128 + q * 8]);
    }
    asm volatile("cp.async.commit_group;");
#pragma unroll
    for (int t = 1; t < 4; t++) {
#pragma unroll
        for (int cch = 0; cch < 2; cch++) {
            int idx = tid + cch * 256;
            int row = idx >> 2, q = idx & 3;
            cp_async16((uint32_t)__cvta_generic_to_shared(&sA[(t * 128 + row) * 40 + q * 8]),
                       &A[(size_t)(m0 + row) * 128 + t * 32 + q * 8]);
        }
        asm volatile("cp.async.commit_group;");
    }

    float c[2][NJ][4];
#pragma unroll
    for (int i = 0; i < 2; i++)
#pragma unroll
        for (int j = 0; j < NJ; j++)
#pragma unroll
            for (int q = 0; q < 4; q++) c[i][j][q] = 0.f;

#pragma unroll
    for (int t = 0; t < 4; t++) {
        if (t == 0)      asm volatile("cp.async.wait_group 3;");
        else if (t == 1) asm volatile("cp.async.wait_group 2;");
        else if (t == 2) asm volatile("cp.async.wait_group 1;");
        else             asm volatile("cp.async.wait_group 0;");
        __syncthreads();
#pragma unroll
        for (int k16 = 0; k16 < 32; k16 += 16) {
            int krow = t * 32 + k16;
            uint32_t a[2][4];
#pragma unroll
            for (int i = 0; i < 2; i++) {
                uint32_t addr = (uint32_t)__cvta_generic_to_shared(
                    &sA[(t * 128 + wm + i * 16 + l15) * 40 + k16 + (lane >> 4) * 8]);
                ldsm_x4(a[i], addr);
            }
            uint32_t b[NJ][2];
#pragma unroll
            for (int j = 0; j < NJ; j++) {
                uint32_t addr = (uint32_t)__cvta_generic_to_shared(
                    &sWh[(krow + l15) * WS + wn + j * 8]);
                ldsm_x2t(b[j], addr);
            }
#pragma unroll
            for (int i = 0; i < 2; i++)
#pragma unroll
                for (int j = 0; j < NJ; j++) mma_bf16(c[i][j], a[i], b[j]);
#pragma unroll
            for (int j = 0; j < NJ; j++) {
                uint32_t addr = (uint32_t)__cvta_generic_to_shared(
                    &sWl[(krow + l15) * WS + wn + j * 8]);
                ldsm_x2t(b[j], addr);
            }
#pragma unroll
            for (int i = 0; i < 2; i++)
#pragma unroll
                for (int j = 0; j < NJ; j++) mma_bf16(c[i][j], a[i], b[j]);
        }
    }

#pragma unroll
    for (int i = 0; i < 2; i++) {
        int r0 = m0 + wm + i * 16 + grp;
        int r1 = r0 + 8;
#pragma unroll
        for (int j = 0; j < NJ; j++) {
            int col = wn + j * 8 + tig * 2;
            if (r0 < M) *(__half2*)&C[(size_t)r0 * BN + col] = __floats2half2_rn(c[i][j][0], c[i][j][1]);
            if (r1 < M) *(__half2*)&C[(size_t)r1 * BN + col] = __floats2half2_rn(c[i][j][2], c[i][j][3]);
        }
    }
}

// ---------------- aggregation (R7 form: interleaved edges, unroll-8 zero-pad) ----------------
__device__ __forceinline__ float4 h4_to_f4(uint2 v, float4 acc, float w) {
    float2 a = __half22float2(*(__half2*)&v.x);
    float2 b = __half22float2(*(__half2*)&v.y);
    acc.x += w * a.x; acc.y += w * a.y; acc.z += w * b.x; acc.w += w * b.y;
    return acc;
}

__global__ __launch_bounds__(256) void k_agg128(const __half* __restrict__ H,
                                                const float* __restrict__ bias,
                                                __nv_bfloat16* __restrict__ out, int n) {
    int warp = (blockIdx.x * blockDim.x + threadIdx.x) >> 5;
    if (warp >= n) return;
    int lane = threadIdx.x & 31;
    const uint2* H2 = (const uint2*)H;
    float sw = g_selfw[warp];
    float4 acc = h4_to_f4(H2[(size_t)warp * 32 + lane], make_float4(0, 0, 0, 0), sw);
    int beg = g_rowptr[warp], end = g_rowptr[warp + 1];
    for (int base = beg; base < end; base += 32) {
        int m = end - base; if (m > 32) m = 32;
        int mr = (m + 7) & ~7;
        int s = 0; float wgt = 0.f;
        if (lane < m) { int2 ed = g_edge[base + lane]; s = ed.x; wgt = __int_as_float(ed.y); }
        for (int j = 0; j < mr; j += 8) {
            int si[8]; float wi[8]; uint2 gv[8];
#pragma unroll
            for (int u = 0; u < 8; u++) {
                si[u] = __shfl_sync(0xffffffffu, s, j + u);
                wi[u] = __shfl_sync(0xffffffffu, wgt, j + u);
            }
#pragma unroll
            for (int u = 0; u < 8; u++) gv[u] = H2[(size_t)si[u] * 32 + lane];
#pragma unroll
            for (int u = 0; u < 8; u++) acc = h4_to_f4(gv[u], acc, wi[u]);
        }
    }
    float4 b4 = ((const float4*)bias)[lane];
    acc.x = fmaxf(acc.x + b4.x, 0.f);
    acc.y = fmaxf(acc.y + b4.y, 0.f);
    acc.z = fmaxf(acc.z + b4.z, 0.f);
    acc.w = fmaxf(acc.w + b4.w, 0.f);
    __nv_bfloat162 o0 = __float22bfloat162_rn(make_float2(acc.x, acc.y));
    __nv_bfloat162 o1 = __float22bfloat162_rn(make_float2(acc.z, acc.w));
    uint2 o; o.x = *(uint32_t*)&o0; o.y = *(uint32_t*)&o1;
    ((uint2*)out)[(size_t)warp * 32 + lane] = o;
}

__global__ __launch_bounds__(256) void k_agg64(const __half* __restrict__ H,
                                               const float* __restrict__ bias,
                                               float* __restrict__ out, int n) {
    int warp = (blockIdx.x * blockDim.x + threadIdx.x) >> 5;
    if (warp >= n) return;
    int lane = threadIdx.x & 31;
    const uint32_t* H1 = (const uint32_t*)H;
    float sw = g_selfw[warp];
    uint32_t hv = H1[(size_t)warp * 32 + lane];
    float2 f0 = __half22float2(*(__half2*)&hv);
    float2 acc = make_float2(sw * f0.x, sw * f0.y);
    int beg = g_rowptr[warp], end = g_rowptr[warp + 1];
    for (int base = beg; base < end; base += 32) {
        int m = end - base; if (m > 32) m = 32;
        int mr = (m + 7) & ~7;
        int s = 0; float wgt = 0.f;
        if (lane < m) { int2 ed = g_edge[base + lane]; s = ed.x; wgt = __int_as_float(ed.y); }
        for (int j = 0; j < mr; j += 8) {
            int si[8]; float wi[8]; uint32_t gv[8];
#pragma unroll
            for (int u = 0; u < 8; u++) {
                si[u] = __shfl_sync(0xffffffffu, s, j + u);
                wi[u] = __shfl_sync(0xffffffffu, wgt, j + u);
            }
#pragma unroll
            for (int u = 0; u < 8; u++) gv[u] = H1[(size_t)si[u] * 32 + lane];
#pragma unroll
            for (int u = 0; u < 8; u++) {
                float2 a0 = __half22float2(*(__half2*)&gv[u]);
                acc.x += wi[u] * a0.x; acc.y += wi[u] * a0.y;
            }
        }
    }
    float2 b2 = ((const float2*)bias)[lane];
    acc.x += b2.x; acc.y += b2.y;
    ((float2*)out)[(size_t)warp * 32 + lane] = acc;
}

// ---------------- global mean pool ----------------
__global__ void k_pool(const float* __restrict__ Hout, float* __restrict__ out) {
    int g = blockIdx.x;
    int t = threadIdx.x;
    int f = t & 63, grp = t >> 6;
    __shared__ float sh[256];
    int s = g_gstart[g], e = g_gend[g];
    float acc = 0.f;
    if (s < e) {
        for (int i = s + grp; i < e; i += 4) acc += Hout[(size_t)i * 64 + f];
    }
    sh[t] = acc;
    __syncthreads();
    if (grp == 0) {
        float v = sh[f] + sh[64 + f] + sh[128 + f] + sh[192 + f];
        int cnt = (s < e) ? (e - s) : 0;
        float denom = (cnt > 0) ? (float)cnt : 1.f;
        out[g * 64 + f] = v / denom;
    }
}

// ---------------- launch ----------------
extern "C" void kernel_launch(void* const* d_in, const int* in_sizes, int n_in,
                              void* d_out, int out_size) {
    const float* x  = (const float*)d_in[0];
    const void*  ei = d_in[1];
    const void*  batch = d_in[2];
    const float* W1 = (const float*)d_in[3];
    const float* b1 = (const float*)d_in[4];
    const float* W2 = (const float*)d_in[5];
    const float* b2 = (const float*)d_in[6];
    const float* W3 = (const float*)d_in[7];
    const float* b3 = (const float*)d_in[8];
    float* out = (float*)d_out;

    int n = in_sizes[0] / FDIM;
    int e = in_sizes[1] / 2;
    if (n > NMAX) n = NMAX;
    if (e > EMAX) e = EMAX;

    int ge  = (e + 255) / 256;
    int nch = (n + 1023) / 1024;
    int total4 = n * FDIM / 4;

    void* p;
    cudaGetSymbolAddress(&p, g_Th);  __half* pTh = (__half*)p;
    cudaGetSymbolAddress(&p, g_Gh);  __nv_bfloat16* pGh = (__nv_bfloat16*)p;
    cudaGetSymbolAddress(&p, g_Xh);  __nv_bfloat16* pXh = (__nv_bfloat16*)p;
    cudaGetSymbolAddress(&p, g_G);   float* pG = (float*)p;
    cudaGetSymbolAddress(&p, g_W1h); __nv_bfloat16* pW1h = (__nv_bfloat16*)p;
    cudaGetSymbolAddress(&p, g_W1l); __nv_bfloat16* pW1l = (__nv_bfloat16*)p;
    cudaGetSymbolAddress(&p, g_W2h); __nv_bfloat16* pW2h = (__nv_bfloat16*)p;
    cudaGetSymbolAddress(&p, g_W2l); __nv_bfloat16* pW2l = (__nv_bfloat16*)p;
    cudaGetSymbolAddress(&p, g_W3h); __nv_bfloat16* pW3h = (__nv_bfloat16*)p;
    cudaGetSymbolAddress(&p, g_W3l); __nv_bfloat16* pW3l = (__nv_bfloat16*)p;
    cudaGetSymbolAddress(&p, g_cntflags); int* pCnt = (int*)p;

    const int SMEM128 = 2 * 128 * (128 + 8) * 2 + 4 * 128 * 40 * 2;  // 110592
    const int SMEM64  = 2 * 128 * (64 + 8) * 2 + 4 * 128 * 40 * 2;   // 77824
    cudaFuncSetAttribute(k_gemm_bf<128>, cudaFuncAttributeMaxDynamicSharedMemorySize, SMEM128);
    cudaFuncSetAttribute(k_gemm_bf<64>,  cudaFuncAttributeMaxDynamicSharedMemorySize, SMEM64);

    int ggemm = (n + 127) / 128;
    int gagg  = (n * 32 + 255) / 256;

    cudaMemsetAsync(pCnt, 0, (NMAX + 128) * sizeof(int));               // cnt + scan flags
    k_fuse1<<<(total4 + 255) / 256, 256>>>(x, ei, batch, W1, W2, W3, n, e, total4);  // K1
    k_scan<<<nch, 256>>>(n);                                            // K2
    k_build<<<ge, 256>>>(e);                                            // K3
    k_gemm_bf<128><<<ggemm, 256, SMEM128>>>(pXh, pW1h, pW1l, pTh, n);   // K4 <- ncu slot
    k_agg128<<<gagg, 256>>>(pTh, b1, pGh, n);                           // K5
    k_gemm_bf<128><<<ggemm, 256, SMEM128>>>(pGh, pW2h, pW2l, pTh, n);   // K6
    k_agg128<<<gagg, 256>>>(pTh, b2, pGh, n);                           // K7
    k_gemm_bf<64><<<ggemm, 256, SMEM64>>>(pGh, pW3h, pW3l, pTh, n);     // K8
    k_agg64<<<gagg, 256>>>(pTh, b3, pG, n);                             // K9
    k_pool<<<NGR, 256>>>(pG, out);                                      // K10
}

// round 13
// speedup vs baseline: 1.0707x; 1.0020x over previous
#include <cuda_runtime.h>
#include <cuda_fp16.h>
#include <cuda_bf16.h>
#include <cstdint>
#include <limits.h>

#define NMAX 100000
#define NPAD 100096   // 782 * 128: gemm2/3 A-tile cp.async never reads past g_Gh
#define EMAX 1600000
#define NGR  64
#define FDIM 128
#define FLAGBIT 0x80000000u

// ---------------- device scratch ----------------
static __device__ __half         g_Th[(size_t)NPAD * FDIM];
static __device__ __nv_bfloat16  g_Gh[(size_t)NPAD * FDIM];
static __device__ float          g_G[(size_t)NMAX * 64];
static __device__ int    g_cntflags[NMAX + 128];   // [0..n)=cnt, [NMAX..]=scan flags (memset 0)
static __device__ int    g_rowptr[NMAX + 1];
static __device__ int    g_cursor[NMAX];
static __device__ int2   g_edge[EMAX];             // interleaved {src, weight-bits}
static __device__ float  g_dinv[NMAX];
static __device__ float  g_selfw[NMAX];
static __device__ int    g_gstart[NGR];
static __device__ int    g_gend[NGR];
static __device__ int    g_src32[EMAX];
static __device__ int    g_dst32[EMAX];

// ---------------- common GEMM helpers ----------------
__device__ __forceinline__ void mma_bf16(float* c, const uint32_t* a, const uint32_t* b) {
    asm volatile("mma.sync.aligned.m16n8k16.row.col.f32.bf16.bf16.f32 "
        "{%0,%1,%2,%3}, {%4,%5,%6,%7}, {%8,%9}, {%0,%1,%2,%3};"
        : "+f"(c[0]), "+f"(c[1]), "+f"(c[2]), "+f"(c[3])
        : "r"(a[0]), "r"(a[1]), "r"(a[2]), "r"(a[3]), "r"(b[0]), "r"(b[1]));
}
__device__ __forceinline__ void ldsm_x4(uint32_t* r, uint32_t addr) {
    asm volatile("ldmatrix.sync.aligned.m8n8.x4.shared.b16 {%0,%1,%2,%3}, [%4];"
        : "=r"(r[0]), "=r"(r[1]), "=r"(r[2]), "=r"(r[3]) : "r"(addr));
}
__device__ __forceinline__ void ldsm_x2t(uint32_t* r, uint32_t addr) {
    asm volatile("ldmatrix.sync.aligned.m8n8.x2.trans.shared.b16 {%0,%1}, [%2];"
        : "=r"(r[0]), "=r"(r[1]) : "r"(addr));
}
__device__ __forceinline__ void cp_async16(uint32_t dst, const void* src) {
    asm volatile("cp.async.ca.shared.global [%0], [%1], 16;" :: "r"(dst), "l"(src));
}
// fp32x4 -> bf16 hi(4) + lo(4), stored to smem
__device__ __forceinline__ void split_store(__nv_bfloat16* ph, __nv_bfloat16* pl, float4 v) {
    __nv_bfloat162 h0 = __float22bfloat162_rn(make_float2(v.x, v.y));
    __nv_bfloat162 h1 = __float22bfloat162_rn(make_float2(v.z, v.w));
    float2 r0 = make_float2(v.x - __low2float(h0), v.y - __high2float(h0));
    float2 r1 = make_float2(v.z - __low2float(h1), v.w - __high2float(h1));
    *(__nv_bfloat162*)ph       = h0;
    *(__nv_bfloat162*)(ph + 2) = h1;
    *(__nv_bfloat162*)pl       = __float22bfloat162_rn(r0);
    *(__nv_bfloat162*)(pl + 2) = __float22bfloat162_rn(r1);
}

// ---------------- K1: gemm1 (fp32 A inline-cvt, fp32 W inline-split) + ALL preprocessing ----
// Side work (grid-stride): int64 detect, edge histogram + int32 stash, graph bounds.
__global__ __launch_bounds__(256) void k_gemm1(
    const float* __restrict__ A, const float* __restrict__ W,
    const void* __restrict__ ei, const void* __restrict__ batch,
    __half* __restrict__ C, int M, int e) {
    constexpr int BN = 128, NJ = 8, WS = 136;
    extern __shared__ __nv_bfloat16 smem[];
    __nv_bfloat16* sWh = smem;                 // [128][136]
    __nv_bfloat16* sWl = smem + 128 * WS;
    __nv_bfloat16* sA  = smem + 2 * 128 * WS;  // [128][136]
    __shared__ int s_is64;

    int tid = threadIdx.x;
    if (tid == 0) {
        const long long* p = (const long long*)ei;
        int ok = 1;
        int m = e < 8 ? e : 8;
        for (int k = 0; k < m; k++) {
            long long v = p[k];
            if (v < 0 || v >= (long long)M) ok = 0;
        }
        s_is64 = ok;
    }
    __syncthreads();
    int is64 = s_is64;
    int m0 = blockIdx.x * 128;

    // W fp32 -> hi/lo smem (4096 float4, 16/thread; all-CTA L2 hits)
#pragma unroll
    for (int it = 0; it < 16; it++) {
        int idx = tid + it * 256;
        int r = idx >> 5, q = idx & 31;
        float4 v = ((const float4*)W)[idx];
        split_store(&sWh[r * WS + q * 4], &sWl[r * WS + q * 4], v);
    }
    // A fp32 -> bf16 smem (this block's 128x128 tile, row-guarded)
#pragma unroll
    for (int it = 0; it < 16; it++) {
        int idx = tid + it * 256;
        int r = idx >> 5, q = idx & 31;
        int row = m0 + r;
        float4 v = make_float4(0.f, 0.f, 0.f, 0.f);
        if (row < M) v = ((const float4*)A)[(size_t)row * 32 + q];
        __nv_bfloat162 h0 = __float22bfloat162_rn(make_float2(v.x, v.y));
        __nv_bfloat162 h1 = __float22bfloat162_rn(make_float2(v.z, v.w));
        *(__nv_bfloat162*)&sA[r * WS + q * 4]     = h0;
        *(__nv_bfloat162*)&sA[r * WS + q * 4 + 2] = h1;
    }

    // side work: edge histogram + int32 stash
    int nt = gridDim.x * 256;
    for (int i = blockIdx.x * 256 + tid; i < e; i += nt) {
        int s, d;
        if (is64) {
            const long long* p = (const long long*)ei;
            s = (int)p[i]; d = (int)p[(size_t)e + i];
        } else {
            const int* p = (const int*)ei;
            s = p[i]; d = p[(size_t)e + i];
        }
        g_src32[i] = s;
        g_dst32[i] = d;
        atomicAdd(&g_cntflags[d], 1);
    }
    // side work: graph bounds (sorted batch -> deterministic single writers)
    for (int i = blockIdx.x * 256 + tid; i < M; i += nt) {
        int b, bp;
        if (is64) {
            const long long* p = (const long long*)batch;
            b = (int)p[i];
            bp = (i > 0) ? (int)p[i - 1] : -1;
        } else {
            const int* p = (const int*)batch;
            b = p[i];
            bp = (i > 0) ? p[i - 1] : -1;
        }
        if (i == 0) {
            g_gstart[b] = 0;
            for (int q = 0; q < b; q++) { g_gstart[q] = 0; g_gend[q] = 0; }
        } else if (bp != b) {
            g_gend[bp] = i;
            g_gstart[b] = i;
            for (int q = bp + 1; q < b; q++) { g_gstart[q] = i; g_gend[q] = i; }
        }
        if (i == M - 1) {
            g_gend[b] = M;
            for (int q = b + 1; q < NGR; q++) { g_gstart[q] = M; g_gend[q] = M; }
        }
    }
    __syncthreads();

    int w = tid >> 5, lane = tid & 31;
    int grp = lane >> 2, tig = lane & 3;
    int wm = (w & 3) * 32;
    int wn = (w >> 2) * (NJ * 8);
    int l15 = lane & 15;

    float c[2][NJ][4];
#pragma unroll
    for (int i = 0; i < 2; i++)
#pragma unroll
        for (int j = 0; j < NJ; j++)
#pragma unroll
            for (int q = 0; q < 4; q++) c[i][j][q] = 0.f;

#pragma unroll
    for (int k16 = 0; k16 < 128; k16 += 16) {
        uint32_t a[2][4];
#pragma unroll
        for (int i = 0; i < 2; i++) {
            uint32_t addr = (uint32_t)__cvta_generic_to_shared(
                &sA[(wm + i * 16 + l15) * WS + k16 + (lane >> 4) * 8]);
            ldsm_x4(a[i], addr);
        }
        uint32_t b[NJ][2];
#pragma unroll
        for (int j = 0; j < NJ; j++) {
            uint32_t addr = (uint32_t)__cvta_generic_to_shared(
                &sWh[(k16 + l15) * WS + wn + j * 8]);
            ldsm_x2t(b[j], addr);
        }
#pragma unroll
        for (int i = 0; i < 2; i++)
#pragma unroll
            for (int j = 0; j < NJ; j++) mma_bf16(c[i][j], a[i], b[j]);
#pragma unroll
        for (int j = 0; j < NJ; j++) {
            uint32_t addr = (uint32_t)__cvta_generic_to_shared(
                &sWl[(k16 + l15) * WS + wn + j * 8]);
            ldsm_x2t(b[j], addr);
        }
#pragma unroll
        for (int i = 0; i < 2; i++)
#pragma unroll
            for (int j = 0; j < NJ; j++) mma_bf16(c[i][j], a[i], b[j]);
    }

#pragma unroll
    for (int i = 0; i < 2; i++) {
        int r0 = m0 + wm + i * 16 + grp;
        int r1 = r0 + 8;
#pragma unroll
        for (int j = 0; j < NJ; j++) {
            int col = wn + j * 8 + tig * 2;
            if (r0 < M) *(__half2*)&C[(size_t)r0 * BN + col] = __floats2half2_rn(c[i][j][0], c[i][j][1]);
            if (r1 < M) *(__half2*)&C[(size_t)r1 * BN + col] = __floats2half2_rn(c[i][j][2], c[i][j][3]);
        }
    }
}

// ---------------- K2: single-kernel decoupled-lookback scan (+ dinv/selfw/cursor) ----------------
__global__ void k_scan(int n) {
    __shared__ int sh[256];
    __shared__ int s_base;
    int b = blockIdx.x, t = threadIdx.x;
    int idx0 = b * 1024 + t * 4;
    int c[4]; int tot = 0;
#pragma unroll
    for (int j = 0; j < 4; j++) {
        int id = idx0 + j;
        c[j] = (id < n) ? g_cntflags[id] : 0;
        tot += c[j];
    }
    sh[t] = tot;
    __syncthreads();
    for (int d = 1; d < 256; d <<= 1) {
        int v = (t >= d) ? sh[t - d] : 0;
        __syncthreads();
        sh[t] += v;
        __syncthreads();
    }
    int incl = sh[t];
    int agg  = sh[255];
    if (t == 0) atomicExch(&g_cntflags[NMAX + b], (int)((unsigned)agg | FLAGBIT));
    int partial = 0;
    for (int j = t; j < b; j += 256) {
        int v;
        do { v = *(volatile int*)&g_cntflags[NMAX + j]; } while (!((unsigned)v & FLAGBIT));
        partial += (int)((unsigned)v & ~FLAGBIT);
    }
    __syncthreads();
    sh[t] = partial;
    __syncthreads();
    for (int d = 128; d > 0; d >>= 1) {
        if (t < d) sh[t] += sh[t + d];
        __syncthreads();
    }
    if (t == 0) s_base = sh[0];
    __syncthreads();
    int run = s_base + incl - tot;
#pragma unroll
    for (int j = 0; j < 4; j++) {
        int id = idx0 + j;
        if (id < n) {
            g_rowptr[id] = run;
            g_cursor[id] = run;
            float di = rsqrtf((float)(c[j] + 1));
            g_dinv[id] = di;
            g_selfw[id] = di * di;
            run += c[j];
            if (id == n - 1) g_rowptr[n] = run;
        }
    }
}

// ---------------- K3: CSR build ----------------
__global__ void k_build(int e) {
    int i = blockIdx.x * blockDim.x + threadIdx.x;
    if (i >= e) return;
    int s = g_src32[i], d = g_dst32[i];
    float w = g_dinv[s] * g_dinv[d];
    int pos = atomicAdd(&g_cursor[d], 1);
    g_edge[pos] = make_int2(s, __float_as_int(w));
}

// ---------------- gemm2/3: A bf16 cp.async pipelined, W fp32 inline-split ----------------
template <int BN>
__global__ __launch_bounds__(256) void k_gemm_bf(const __nv_bfloat16* __restrict__ A,
                                                 const float* __restrict__ W,
                                                 __half* __restrict__ C, int M) {
    constexpr int NJ = BN / 16;
    constexpr int WS = BN + 8;
    extern __shared__ __nv_bfloat16 smem[];
    __nv_bfloat16* sWh = smem;
    __nv_bfloat16* sWl = smem + 128 * WS;
    __nv_bfloat16* sA  = smem + 2 * 128 * WS;  // [4][128][40]

    int tid = threadIdx.x;
    int w = tid >> 5, lane = tid & 31;
    int grp = lane >> 2, tig = lane & 3;
    int wm = (w & 3) * 32;
    int wn = (w >> 2) * (NJ * 8);
    int m0 = blockIdx.x * 128;
    int l15 = lane & 15;

    // A tiles 0..3 as 4 cp.async groups (issued first, fully async)
#pragma unroll
    for (int t = 0; t < 4; t++) {
#pragma unroll
        for (int cch = 0; cch < 2; cch++) {
            int idx = tid + cch * 256;
            int row = idx >> 2, q = idx & 3;
            cp_async16((uint32_t)__cvta_generic_to_shared(&sA[(t * 128 + row) * 40 + q * 8]),
                       &A[(size_t)(m0 + row) * 128 + t * 32 + q * 8]);
        }
        asm volatile("cp.async.commit_group;");
    }
    // W fp32 -> hi/lo smem (overlapped with A in flight; L2 hits)
#pragma unroll
    for (int it = tid; it < 128 * BN / 4; it += 256) {
        int r = it / (BN / 4), q = it % (BN / 4);
        float4 v = ((const float4*)W)[it];
        split_store(&sWh[r * WS + q * 4], &sWl[r * WS + q * 4], v);
    }

    float c[2][NJ][4];
#pragma unroll
    for (int i = 0; i < 2; i++)
#pragma unroll
        for (int j = 0; j < NJ; j++)
#pragma unroll
            for (int q = 0; q < 4; q++) c[i][j][q] = 0.f;

#pragma unroll
    for (int t = 0; t < 4; t++) {
        if (t == 0)      asm volatile("cp.async.wait_group 3;");
        else if (t == 1) asm volatile("cp.async.wait_group 2;");
        else if (t == 2) asm volatile("cp.async.wait_group 1;");
        else             asm volatile("cp.async.wait_group 0;");
        __syncthreads();
#pragma unroll
        for (int k16 = 0; k16 < 32; k16 += 16) {
            int krow = t * 32 + k16;
            uint32_t a[2][4];
#pragma unroll
            for (int i = 0; i < 2; i++) {
                uint32_t addr = (uint32_t)__cvta_generic_to_shared(
                    &sA[(t * 128 + wm + i * 16 + l15) * 40 + k16 + (lane >> 4) * 8]);
                ldsm_x4(a[i], addr);
            }
            uint32_t b[NJ][2];
#pragma unroll
            for (int j = 0; j < NJ; j++) {
                uint32_t addr = (uint32_t)__cvta_generic_to_shared(
                    &sWh[(krow + l15) * WS + wn + j * 8]);
                ldsm_x2t(b[j], addr);
            }
#pragma unroll
            for (int i = 0; i < 2; i++)
#pragma unroll
                for (int j = 0; j < NJ; j++) mma_bf16(c[i][j], a[i], b[j]);
#pragma unroll
            for (int j = 0; j < NJ; j++) {
                uint32_t addr = (uint32_t)__cvta_generic_to_shared(
                    &sWl[(krow + l15) * WS + wn + j * 8]);
                ldsm_x2t(b[j], addr);
            }
#pragma unroll
            for (int i = 0; i < 2; i++)
#pragma unroll
                for (int j = 0; j < NJ; j++) mma_bf16(c[i][j], a[i], b[j]);
        }
    }

#pragma unroll
    for (int i = 0; i < 2; i++) {
        int r0 = m0 + wm + i * 16 + grp;
        int r1 = r0 + 8;
#pragma unroll
        for (int j = 0; j < NJ; j++) {
            int col = wn + j * 8 + tig * 2;
            if (r0 < M) *(__half2*)&C[(size_t)r0 * BN + col] = __floats2half2_rn(c[i][j][0], c[i][j][1]);
            if (r1 < M) *(__half2*)&C[(size_t)r1 * BN + col] = __floats2half2_rn(c[i][j][2], c[i][j][3]);
        }
    }
}

// ---------------- aggregation (proven R7 form) ----------------
__device__ __forceinline__ float4 h4_to_f4(uint2 v, float4 acc, float w) {
    float2 a = __half22float2(*(__half2*)&v.x);
    float2 b = __half22float2(*(__half2*)&v.y);
    acc.x += w * a.x; acc.y += w * a.y; acc.z += w * b.x; acc.w += w * b.y;
    return acc;
}

__global__ __launch_bounds__(256) void k_agg128(const __half* __restrict__ H,
                                                const float* __restrict__ bias,
                                                __nv_bfloat16* __restrict__ out, int n) {
    int warp = (blockIdx.x * blockDim.x + threadIdx.x) >> 5;
    if (warp >= n) return;
    int lane = threadIdx.x & 31;
    const uint2* H2 = (const uint2*)H;
    float sw = g_selfw[warp];
    float4 acc = h4_to_f4(H2[(size_t)warp * 32 + lane], make_float4(0, 0, 0, 0), sw);
    int beg = g_rowptr[warp], end = g_rowptr[warp + 1];
    for (int base = beg; base < end; base += 32) {
        int m = end - base; if (m > 32) m = 32;
        int mr = (m + 7) & ~7;
        int s = 0; float wgt = 0.f;
        if (lane < m) { int2 ed = g_edge[base + lane]; s = ed.x; wgt = __int_as_float(ed.y); }
        for (int j = 0; j < mr; j += 8) {
            int si[8]; float wi[8]; uint2 gv[8];
#pragma unroll
            for (int u = 0; u < 8; u++) {
                si[u] = __shfl_sync(0xffffffffu, s, j + u);
                wi[u] = __shfl_sync(0xffffffffu, wgt, j + u);
            }
#pragma unroll
            for (int u = 0; u < 8; u++) gv[u] = H2[(size_t)si[u] * 32 + lane];
#pragma unroll
            for (int u = 0; u < 8; u++) acc = h4_to_f4(gv[u], acc, wi[u]);
        }
    }
    float4 b4 = ((const float4*)bias)[lane];
    acc.x = fmaxf(acc.x + b4.x, 0.f);
    acc.y = fmaxf(acc.y + b4.y, 0.f);
    acc.z = fmaxf(acc.z + b4.z, 0.f);
    acc.w = fmaxf(acc.w + b4.w, 0.f);
    __nv_bfloat162 o0 = __float22bfloat162_rn(make_float2(acc.x, acc.y));
    __nv_bfloat162 o1 = __float22bfloat162_rn(make_float2(acc.z, acc.w));
    uint2 o; o.x = *(uint32_t*)&o0; o.y = *(uint32_t*)&o1;
    ((uint2*)out)[(size_t)warp * 32 + lane] = o;
}

__global__ __launch_bounds__(256) void k_agg64(const __half* __restrict__ H,
                                               const float* __restrict__ bias,
                                               float* __restrict__ out, int n) {
    int warp = (blockIdx.x * blockDim.x + threadIdx.x) >> 5;
    if (warp >= n) return;
    int lane = threadIdx.x & 31;
    const uint32_t* H1 = (const uint32_t*)H;
    float sw = g_selfw[warp];
    uint32_t hv = H1[(size_t)warp * 32 + lane];
    float2 f0 = __half22float2(*(__half2*)&hv);
    float2 acc = make_float2(sw * f0.x, sw * f0.y);
    int beg = g_rowptr[warp], end = g_rowptr[warp + 1];
    for (int base = beg; base < end; base += 32) {
        int m = end - base; if (m > 32) m = 32;
        int mr = (m + 7) & ~7;
        int s = 0; float wgt = 0.f;
        if (lane < m) { int2 ed = g_edge[base + lane]; s = ed.x; wgt = __int_as_float(ed.y); }
        for (int j = 0; j < mr; j += 8) {
            int si[8]; float wi[8]; uint32_t gv[8];
#pragma unroll
            for (int u = 0; u < 8; u++) {
                si[u] = __shfl_sync(0xffffffffu, s, j + u);
                wi[u] = __shfl_sync(0xffffffffu, wgt, j + u);
            }
#pragma unroll
            for (int u = 0; u < 8; u++) gv[u] = H1[(size_t)si[u] * 32 + lane];
#pragma unroll
            for (int u = 0; u < 8; u++) {
                float2 a0 = __half22float2(*(__half2*)&gv[u]);
                acc.x += wi[u] * a0.x; acc.y += wi[u] * a0.y;
            }
        }
    }
    float2 b2 = ((const float2*)bias)[lane];
    acc.x += b2.x; acc.y += b2.y;
    ((float2*)out)[(size_t)warp * 32 + lane] = acc;
}

// ---------------- global mean pool ----------------
__global__ void k_pool(const float* __restrict__ Hout, float* __restrict__ out) {
    int g = blockIdx.x;
    int t = threadIdx.x;
    int f = t & 63, grp = t >> 6;
    __shared__ float sh[256];
    int s = g_gstart[g], e = g_gend[g];
    float acc = 0.f;
    if (s < e) {
        for (int i = s + grp; i < e; i += 4) acc += Hout[(size_t)i * 64 + f];
    }
    sh[t] = acc;
    __syncthreads();
    if (grp == 0) {
        float v = sh[f] + sh[64 + f] + sh[128 + f] + sh[192 + f];
        int cnt = (s < e) ? (e - s) : 0;
        float denom = (cnt > 0) ? (float)cnt : 1.f;
        out[g * 64 + f] = v / denom;
    }
}

// ---------------- launch ----------------
extern "C" void kernel_launch(void* const* d_in, const int* in_sizes, int n_in,
                              void* d_out, int out_size) {
    const float* x  = (const float*)d_in[0];
    const void*  ei = d_in[1];
    const void*  batch = d_in[2];
    const float* W1 = (const float*)d_in[3];
    const float* b1 = (const float*)d_in[4];
    const float* W2 = (const float*)d_in[5];
    const float* b2 = (const float*)d_in[6];
    const float* W3 = (const float*)d_in[7];
    const float* b3 = (const float*)d_in[8];
    float* out = (float*)d_out;

    int n = in_sizes[0] / FDIM;
    int e = in_sizes[1] / 2;
    if (n > NMAX) n = NMAX;
    if (e > EMAX) e = EMAX;

    int ge  = (e + 255) / 256;
    int nch = (n + 1023) / 1024;

    void* p;
    cudaGetSymbolAddress(&p, g_Th);  __half* pTh = (__half*)p;
    cudaGetSymbolAddress(&p, g_Gh);  __nv_bfloat16* pGh = (__nv_bfloat16*)p;
    cudaGetSymbolAddress(&p, g_G);   float* pG = (float*)p;
    cudaGetSymbolAddress(&p, g_cntflags); int* pCnt = (int*)p;

    const int SMEM_G1  = 3 * 128 * 136 * 2;                          // 104448
    const int SMEM128  = 2 * 128 * (128 + 8) * 2 + 4 * 128 * 40 * 2; // 110592
    const int SMEM64   = 2 * 128 * (64 + 8) * 2 + 4 * 128 * 40 * 2;  // 77824
    cudaFuncSetAttribute(k_gemm1,       cudaFuncAttributeMaxDynamicSharedMemorySize, SMEM_G1);
    cudaFuncSetAttribute(k_gemm_bf<128>, cudaFuncAttributeMaxDynamicSharedMemorySize, SMEM128);
    cudaFuncSetAttribute(k_gemm_bf<64>,  cudaFuncAttributeMaxDynamicSharedMemorySize, SMEM64);

    int ggemm = (n + 127) / 128;
    int gagg  = (n * 32 + 255) / 256;

    cudaMemsetAsync(pCnt, 0, (NMAX + 128) * sizeof(int));
    k_gemm1<<<ggemm, 256, SMEM_G1>>>(x, W1, ei, batch, pTh, n, e);      // K1 (gemm + all preproc)
    k_scan<<<nch, 256>>>(n);                                            // K2
    k_build<<<ge, 256>>>(e);                                            // K3
    k_agg128<<<gagg, 256>>>(pTh, b1, pGh, n);                           // K4 <- ncu slot
    k_gemm_bf<128><<<ggemm, 256, SMEM128>>>(pGh, W2, pTh, n);           // K5
    k_agg128<<<gagg, 256>>>(pTh, b2, pGh, n);                           // K6
    k_gemm_bf<64><<<ggemm, 256, SMEM64>>>(pGh, W3, pTh, n);             // K7
    k_agg64<<<gagg, 256>>>(pTh, b3, pG, n);                             // K8
    k_pool<<<NGR, 256>>>(pG, out);                                      // K9
}